// round 13
// baseline (speedup 1.0000x reference)
#include <cuda_runtime.h>

#define BB 1024
#define TT 512
#define H1C 80
#define G1 320
#define H2C 100
#define G2 400

// Scratch (static device arrays: allocation-free per harness rules)
__device__ float g_h1[(size_t)TT * BB * H1C];      // relu(h1): 168 MB, layout [t][b][u]
__device__ float g_xg2[(size_t)TT * BB * G2];      // layer-2 gate pre-acts: 839 MB, [t][b][g]
__device__ float g_h2last[BB * H2C];               // relu(h2) at t=T-1
__device__ int   g_dummy_sink[32];

__device__ __forceinline__ float2 ffma2(float2 d, float2 a, float2 b) {
    unsigned long long dd = *reinterpret_cast<unsigned long long*>(&d);
    unsigned long long aa = *reinterpret_cast<unsigned long long*>(&a);
    unsigned long long bb = *reinterpret_cast<unsigned long long*>(&b);
    asm("fma.rn.f32x2 %0, %1, %2, %0;" : "+l"(dd) : "l"(aa), "l"(bb));
    return *reinterpret_cast<float2*>(&dd);
}

__device__ __forceinline__ float tanha(float x) {
    float y; asm("tanh.approx.f32 %0, %1;" : "=f"(y) : "f"(x)); return y;
}
__device__ __forceinline__ float sigma_(float x) { return fmaf(0.5f, tanha(0.5f * x), 0.5f); }

// ---------------------------------------------------------------------------
// Kernel 1: layer-1 LSTM. 128 CTAs x 8 batches, 512 threads, persistent over T.
// Phase-staggered: 2 independent 4-batch groups; each phase does matvec(g_mv)
// interleaved with activation(g_act) so MUFU/LDS latency hides under FFMA2s.
// W register-resident: 400 mv threads = 5 kg (16 k) x 80 jg (4 j).
// gs[g][kg][bp][par][320]; activation <=1 item/thread.
// ---------------------------------------------------------------------------
__device__ __forceinline__ void lstm1_phase(
    int g_mv, int g_act, int t_act,
    const float (&wreg)[4][16], float& cst,
    float* hs, float* gs, const float* wx, const float* bs, const float* xall,
    bool mvact, int k0, int j0, int kg,
    bool has_item, int ibl, int iu, int b0)
{
    // ---- activation gathers for g_act (hoisted: reads last phase's gs) ----
    float s0, s1, s2, s3;
    if (has_item) {
        const float xv = xall[(g_act * 4 + ibl) * TT + t_act];
        s0 = fmaf(xv, wx[iu],       bs[iu]);
        s1 = fmaf(xv, wx[80 + iu],  bs[80 + iu]);
        s2 = fmaf(xv, wx[160 + iu], bs[160 + iu]);
        s3 = fmaf(xv, wx[240 + iu], bs[240 + iu]);
        const float* gb = gs + g_act * 6400 + (ibl >> 1) * 640 + (ibl & 1) * 320;
#pragma unroll
        for (int q = 0; q < 5; ++q) {
            const float* gq = gb + q * 1280;
            s0 += gq[iu]; s1 += gq[80 + iu]; s2 += gq[160 + iu]; s3 += gq[240 + iu];
        }
    }
    // ---- matvec for g_mv (FFMA2 stream hides the act chain) ----
    float2 a[4][2];
    if (mvact) {
#pragma unroll
        for (int j = 0; j < 4; ++j) { a[j][0] = make_float2(0.f, 0.f); a[j][1] = make_float2(0.f, 0.f); }
        const float* hp = hs + g_mv * 4 + k0 * 8;
#pragma unroll
        for (int k = 0; k < 16; ++k) {
            float4 hv = *(const float4*)(hp + k * 8);   // broadcast, 4 batches
            float2 hq0 = make_float2(hv.x, hv.y);
            float2 hq1 = make_float2(hv.z, hv.w);
#pragma unroll
            for (int j = 0; j < 4; ++j) {
                float2 wd = make_float2(wreg[j][k], wreg[j][k]);
                a[j][0] = ffma2(a[j][0], wd, hq0);
                a[j][1] = ffma2(a[j][1], wd, hq1);
            }
        }
    }
    // ---- activation finish (MUFU.TANH path) ----
    if (has_item) {
        float ig = sigma_(s0), fg = sigma_(s1), gg = tanha(s2), og = sigma_(s3);
        float c = fmaf(fg, cst, ig * gg);
        cst = c;
        float h = og * tanha(c);
        hs[iu * 8 + g_act * 4 + ibl] = h;
        g_h1[(size_t)t_act * (BB * H1C) + (size_t)(b0 + g_act * 4 + ibl) * H1C + iu] = fmaxf(h, 0.0f);
    }
    // ---- store matvec partials ----
    if (mvact) {
        float* gp = gs + g_mv * 6400 + kg * 1280 + j0;
#pragma unroll
        for (int bq = 0; bq < 2; ++bq) {
            *(float4*)(gp + bq * 640)       = make_float4(a[0][bq].x, a[1][bq].x, a[2][bq].x, a[3][bq].x);
            *(float4*)(gp + bq * 640 + 320) = make_float4(a[0][bq].y, a[1][bq].y, a[2][bq].y, a[3][bq].y);
        }
    }
}

__global__ void __launch_bounds__(512, 1)
lstm1_kernel(const float* __restrict__ x, const float* __restrict__ W_ih1,
             const float* __restrict__ W_hh1, const float* __restrict__ b_ih1,
             const float* __restrict__ b_hh1) {
    extern __shared__ float sm[];
    float* wx   = sm;                   // 320
    float* bs   = wx + 320;             // 320
    float* hs   = bs + 320;             // 640    [k][b]
    float* gs   = hs + 640;             // 12800  [g][kg][bp][par][320]
    float* xall = gs + 12800;           // 4096   [b][t]

    const int tid = threadIdx.x;
    const int b0  = blockIdx.x * 8;

    for (int i = tid; i < G1; i += 512) { wx[i] = W_ih1[i]; bs[i] = b_ih1[i] + b_hh1[i]; }
    for (int i = tid; i < 640; i += 512) hs[i] = 0.0f;
    for (int i = tid; i < 12800; i += 512) gs[i] = 0.0f;   // = W_hh1 @ h0 (h0=0)
    for (int i = tid; i < 8 * TT; i += 512) {
        int b = i >> 9, t = i & 511;
        xall[i] = x[(size_t)(b0 + b) * TT + t];
    }

    const bool mvact = tid < 400;
    const int  kg = tid / 80;           // 5 k-groups of 16
    const int  jg = tid - kg * 80;      // 80 j-groups of 4
    const int  j0 = jg * 4;
    const int  k0 = kg * 16;

    float wreg[4][16];
    if (mvact) {
#pragma unroll
        for (int j = 0; j < 4; ++j)
#pragma unroll
            for (int kq = 0; kq < 4; ++kq)
                *(float4*)&wreg[j][kq * 4] =
                    *(const float4*)(W_hh1 + (size_t)(j0 + j) * H1C + k0 + kq * 4);
    }

    const bool has_item = tid < 320;    // items per group: 4 b x 80 u
    const int  ibl = tid / 80;          // local batch 0..3
    const int  iu  = tid - ibl * 80;
    float cst[2] = {0.f, 0.f};
    __syncthreads();

    for (int t = 0; t < TT; ++t) {
        // phase A: matvec g1 @ t, act g0 @ t
        lstm1_phase(1, 0, t, wreg, cst[0], hs, gs, wx, bs, xall,
                    mvact, k0, j0, kg, has_item, ibl, iu, b0);
        __syncthreads();
        // phase B: matvec g0 @ t+1 (harmless overrun at t=TT-1), act g1 @ t
        lstm1_phase(0, 1, t, wreg, cst[1], hs, gs, wx, bs, xall,
                    mvact, k0, j0, kg, has_item, ibl, iu, b0);
        __syncthreads();
    }
}

// ---------------------------------------------------------------------------
// Kernel 2: xg2 = relu(h1) @ W_ih2^T + bias.  Persistent, 148 blocks, 512 thr.
// (fma-bound; unchanged)
// ---------------------------------------------------------------------------
__global__ void __launch_bounds__(512, 1)
xg2_gemm_kernel(const float* __restrict__ W_ih2, const float* __restrict__ b_ih2,
                const float* __restrict__ b_hh2) {
    extern __shared__ float sm[];
    float* Wt   = sm;            // 80*400 = 32000 (transposed W_ih2)
    float* bias = Wt + 32000;    // 400
    float* As   = bias + 400;    // 64*80 = 5120

    const int tid = threadIdx.x;
    for (int i = tid; i < G2 * H1C; i += 512) {
        int jj = i / H1C, k = i - jj * H1C;
        Wt[k * G2 + jj] = W_ih2[i];
    }
    for (int i = tid; i < G2; i += 512) bias[i] = b_ih2[i] + b_hh2[i];

    const int  rg  = tid / 50;
    const int  cg  = tid - rg * 50;
    const bool act = tid < 400;
    const int  NT  = (TT * BB) / 64;   // 8192 tiles

    for (int tile = blockIdx.x; tile < NT; tile += gridDim.x) {
        size_t r0 = (size_t)tile * 64;
        __syncthreads();
        for (int i = tid; i < 64 * H1C; i += 512) As[i] = g_h1[r0 * H1C + i];
        __syncthreads();
        if (act) {
            float2 acc[8][4];
#pragma unroll
            for (int i = 0; i < 8; ++i)
#pragma unroll
                for (int p = 0; p < 4; ++p) acc[i][p] = make_float2(0.f, 0.f);
            const float* ap = As + rg * 8 * H1C;
            const float* wp = Wt + cg * 8;
#pragma unroll 2
            for (int k = 0; k < H1C; ++k) {
                float2 w0 = *(const float2*)(wp + k * G2);
                float2 w1 = *(const float2*)(wp + k * G2 + 2);
                float2 w2 = *(const float2*)(wp + k * G2 + 4);
                float2 w3 = *(const float2*)(wp + k * G2 + 6);
#pragma unroll
                for (int i = 0; i < 8; ++i) {
                    float aval = ap[i * H1C + k];
                    float2 ad = make_float2(aval, aval);
                    acc[i][0] = ffma2(acc[i][0], w0, ad);
                    acc[i][1] = ffma2(acc[i][1], w1, ad);
                    acc[i][2] = ffma2(acc[i][2], w2, ad);
                    acc[i][3] = ffma2(acc[i][3], w3, ad);
                }
            }
            const int c = cg * 8;
#pragma unroll
            for (int i = 0; i < 8; ++i) {
                size_t row = r0 + (size_t)rg * 8 + i;
                float* op = g_xg2 + row * G2 + c;
#pragma unroll
                for (int p = 0; p < 4; ++p) {
                    float2 v = acc[i][p];
                    v.x += bias[c + 2 * p];
                    v.y += bias[c + 2 * p + 1];
                    *(float2*)(op + 2 * p) = v;
                }
            }
        }
    }
}

// ---------------------------------------------------------------------------
// Dummy kernel: keeps lstm2 as the 4th launch for ncu's fixed -s window.
// ---------------------------------------------------------------------------
__global__ void dummy_kernel() {
    if (threadIdx.x == 0) g_dummy_sink[blockIdx.x] = 1;
}

// ---------------------------------------------------------------------------
// Kernel 3: layer-2 LSTM. Phase-staggered like lstm1.
// W register-resident: 500 mv threads = 5 kg (20 k) x 100 jg (4 j).
// gs[g][kg][bp][par][400]; xg prefetched one phase ahead (ping via in-thread order).
// ---------------------------------------------------------------------------
__device__ __forceinline__ void lstm2_phase(
    int g_mv, int g_act, int t_act, int t_next,
    const float (&wreg)[4][20], float& cst, float (&xv)[4],
    float* hs, float* gs,
    bool mvact, int k0, int j0, int kg,
    bool has_item, int ibl, int iu, int b0)
{
    // ---- activation sums for g_act (xv prefetched last phase; gs from last phase) ----
    float s0, s1, s2, s3;
    if (has_item) {
        s0 = xv[0]; s1 = xv[1]; s2 = xv[2]; s3 = xv[3];
        const float* gb = gs + g_act * 8000 + (ibl >> 1) * 800 + (ibl & 1) * 400;
#pragma unroll
        for (int q = 0; q < 5; ++q) {
            const float* gq = gb + q * 1600;
            s0 += gq[iu]; s1 += gq[100 + iu]; s2 += gq[200 + iu]; s3 += gq[300 + iu];
        }
    }
    // ---- prefetch xg for next phase's act = (g_mv, t_next) ----
    if (has_item && t_next < TT) {
        const float* xp = g_xg2 + (size_t)t_next * (BB * G2)
                                + (size_t)(b0 + g_mv * 4 + ibl) * G2 + iu;
        xv[0] = xp[0]; xv[1] = xp[100]; xv[2] = xp[200]; xv[3] = xp[300];
    }
    // ---- matvec for g_mv ----
    float2 a[4][2];
    if (mvact) {
#pragma unroll
        for (int j = 0; j < 4; ++j) { a[j][0] = make_float2(0.f, 0.f); a[j][1] = make_float2(0.f, 0.f); }
        const float* hp = hs + g_mv * 4 + k0 * 8;
#pragma unroll
        for (int k = 0; k < 20; ++k) {
            float4 hv = *(const float4*)(hp + k * 8);   // broadcast, 4 batches
            float2 hq0 = make_float2(hv.x, hv.y);
            float2 hq1 = make_float2(hv.z, hv.w);
#pragma unroll
            for (int j = 0; j < 4; ++j) {
                float2 wd = make_float2(wreg[j][k], wreg[j][k]);
                a[j][0] = ffma2(a[j][0], wd, hq0);
                a[j][1] = ffma2(a[j][1], wd, hq1);
            }
        }
    }
    // ---- activation finish (MUFU.TANH path) ----
    if (has_item) {
        float ig = sigma_(s0), fg = sigma_(s1), gg = tanha(s2), og = sigma_(s3);
        float c = fmaf(fg, cst, ig * gg);
        cst = c;
        float h = og * tanha(c);
        hs[iu * 8 + g_act * 4 + ibl] = h;
        if (t_act == TT - 1) g_h2last[(b0 + g_act * 4 + ibl) * H2C + iu] = fmaxf(h, 0.0f);
    }
    // ---- store matvec partials ----
    if (mvact) {
        float* gp = gs + g_mv * 8000 + kg * 1600 + j0;
#pragma unroll
        for (int bq = 0; bq < 2; ++bq) {
            *(float4*)(gp + bq * 800)       = make_float4(a[0][bq].x, a[1][bq].x, a[2][bq].x, a[3][bq].x);
            *(float4*)(gp + bq * 800 + 400) = make_float4(a[0][bq].y, a[1][bq].y, a[2][bq].y, a[3][bq].y);
        }
    }
}

__global__ void __launch_bounds__(512, 1)
lstm2_kernel(const float* __restrict__ W_hh2) {
    extern __shared__ float sm[];
    float* hs = sm;              // 800    [k][b]
    float* gs = hs + 800;        // 16000  [g][kg][bp][par][400]

    const int tid = threadIdx.x;
    const int b0  = blockIdx.x * 8;

    for (int i = tid; i < 800; i += 512) hs[i] = 0.0f;
    for (int i = tid; i < 16000; i += 512) gs[i] = 0.0f;   // = W_hh2 @ h0 (h0=0)

    const bool mvact = tid < 500;
    const int  kg = tid / 100;          // 5 k-groups of 20
    const int  jg = tid - kg * 100;     // 100 j-groups of 4
    const int  j0 = jg * 4;
    const int  k0 = kg * 20;

    float wreg[4][20];
    if (mvact) {
#pragma unroll
        for (int j = 0; j < 4; ++j)
#pragma unroll
            for (int kq = 0; kq < 5; ++kq)
                *(float4*)&wreg[j][kq * 4] =
                    *(const float4*)(W_hh2 + (size_t)(j0 + j) * H2C + k0 + kq * 4);
    }

    const bool has_item = tid < 400;    // items per group: 4 b x 100 u
    const int  ibl = tid / 100;         // local batch 0..3
    const int  iu  = tid - ibl * 100;
    float cst[2] = {0.f, 0.f};

    // pre-loop prefetch for (g0, t=0)
    float xv[4] = {0.f, 0.f, 0.f, 0.f};
    if (has_item) {
        const float* xp = g_xg2 + (size_t)(b0 + ibl) * G2 + iu;
        xv[0] = xp[0]; xv[1] = xp[100]; xv[2] = xp[200]; xv[3] = xp[300];
    }
    __syncthreads();

    for (int t = 0; t < TT; ++t) {
        // phase A: matvec g1 @ t, act g0 @ t, prefetch (g1, t)
        lstm2_phase(1, 0, t, t, wreg, cst[0], xv, hs, gs,
                    mvact, k0, j0, kg, has_item, ibl, iu, b0);
        __syncthreads();
        // phase B: matvec g0 @ t+1, act g1 @ t, prefetch (g0, t+1)
        lstm2_phase(0, 1, t, t + 1, wreg, cst[1], xv, hs, gs,
                    mvact, k0, j0, kg, has_item, ibl, iu, b0);
        __syncthreads();
    }
}

// ---------------------------------------------------------------------------
// Kernel 4: final MLP head.
// ---------------------------------------------------------------------------
__global__ void fc_kernel(const float* __restrict__ W_l1, const float* __restrict__ b_l1,
                          const float* __restrict__ W_l2, const float* __restrict__ b_l2,
                          float* __restrict__ out) {
    __shared__ float wl1[10 * 100];
    __shared__ float bl1[10], wl2[10], bl2s;
    const int tid = threadIdx.x;
    for (int i = tid; i < 1000; i += 256) wl1[i] = W_l1[i];
    if (tid < 10) { bl1[tid] = b_l1[tid]; wl2[tid] = W_l2[tid]; }
    if (tid == 0) bl2s = b_l2[0];
    __syncthreads();

    const int b = blockIdx.x * 256 + tid;
    float acc[10];
#pragma unroll
    for (int jj = 0; jj < 10; ++jj) acc[jj] = bl1[jj];
    const float* hp = g_h2last + b * H2C;
    for (int k = 0; k < H2C; ++k) {
        float hk = hp[k];
#pragma unroll
        for (int jj = 0; jj < 10; ++jj) acc[jj] = fmaf(wl1[jj * 100 + k], hk, acc[jj]);
    }
    float o = bl2s;
#pragma unroll
    for (int jj = 0; jj < 10; ++jj) o += wl2[jj] * fmaxf(acc[jj], 0.0f);
    out[b] = o;
}

// ---------------------------------------------------------------------------
extern "C" void kernel_launch(void* const* d_in, const int* in_sizes, int n_in,
                              void* d_out, int out_size) {
    const float* x     = (const float*)d_in[0];
    const float* W_ih1 = (const float*)d_in[1];
    const float* W_hh1 = (const float*)d_in[2];
    const float* b_ih1 = (const float*)d_in[3];
    const float* b_hh1 = (const float*)d_in[4];
    const float* W_ih2 = (const float*)d_in[5];
    const float* W_hh2 = (const float*)d_in[6];
    const float* b_ih2 = (const float*)d_in[7];
    const float* b_hh2 = (const float*)d_in[8];
    const float* W_l1  = (const float*)d_in[9];
    const float* b_l1  = (const float*)d_in[10];
    const float* W_l2  = (const float*)d_in[11];
    const float* b_l2  = (const float*)d_in[12];

    const size_t smA = (size_t)(320 + 320 + 640 + 12800 + 4096) * 4;  // 72704 B
    const size_t smG = (size_t)(32000 + 400 + 5120) * 4;              // 150080 B
    const size_t smB = (size_t)(800 + 16000) * 4;                     // 67200 B

    cudaFuncSetAttribute(lstm1_kernel,    cudaFuncAttributeMaxDynamicSharedMemorySize, (int)smA);
    cudaFuncSetAttribute(xg2_gemm_kernel, cudaFuncAttributeMaxDynamicSharedMemorySize, (int)smG);
    cudaFuncSetAttribute(lstm2_kernel,    cudaFuncAttributeMaxDynamicSharedMemorySize, (int)smB);

    lstm1_kernel<<<128, 512, smA>>>(x, W_ih1, W_hh1, b_ih1, b_hh1);
    xg2_gemm_kernel<<<148, 512, smG>>>(W_ih2, b_ih2, b_hh2);
    dummy_kernel<<<1, 32>>>();                                  // capture-window shim
    lstm2_kernel<<<128, 512, smB>>>(W_hh2);
    fc_kernel<<<4, 256>>>(W_l1, b_l1, W_l2, b_l2, (float*)d_out);
}

// round 14
// speedup vs baseline: 1.2842x; 1.2842x over previous
#include <cuda_runtime.h>

#define BB 1024
#define TT 512
#define H1C 80
#define G1 320
#define H2C 100
#define G2 400

// Scratch (static device arrays: allocation-free per harness rules)
__device__ float g_h1[(size_t)TT * BB * H1C];      // relu(h1): 168 MB, layout [t][b][u]
__device__ float g_xg2[(size_t)TT * BB * G2];      // layer-2 gate pre-acts: 839 MB, [t][b][g]
__device__ float g_h2last[BB * H2C];               // relu(h2) at t=T-1
__device__ int   g_dummy_sink[32];

__device__ __forceinline__ float2 ffma2(float2 d, float2 a, float2 b) {
    unsigned long long dd = *reinterpret_cast<unsigned long long*>(&d);
    unsigned long long aa = *reinterpret_cast<unsigned long long*>(&a);
    unsigned long long bb = *reinterpret_cast<unsigned long long*>(&b);
    asm("fma.rn.f32x2 %0, %1, %2, %0;" : "+l"(dd) : "l"(aa), "l"(bb));
    return *reinterpret_cast<float2*>(&dd);
}

__device__ __forceinline__ float tanha(float x) {
    float y; asm("tanh.approx.f32 %0, %1;" : "=f"(y) : "f"(x)); return y;
}
__device__ __forceinline__ float sigma_(float x) { return fmaf(0.5f, tanha(0.5f * x), 0.5f); }

// ---------------------------------------------------------------------------
// Kernel 1: layer-1 LSTM. 128 CTAs x 8 batches, 512 threads, persistent over T.
// W_hh1 REGISTER-RESIDENT: 400 active threads = 5 kg (16 k) x 80 jg (4 j),
// wreg[4][16] loaded once. Batches in 2 half-passes (4 b) to cap accumulators.
// Partials gs[kg][bp][par][320]: coalesced STS.128 stores, stride-1 gathers.
// Activations via MUFU.TANH (R13-validated: rel_err ~3e-7).
// ---------------------------------------------------------------------------
__global__ void __launch_bounds__(512, 1)
lstm1_kernel(const float* __restrict__ x, const float* __restrict__ W_ih1,
             const float* __restrict__ W_hh1, const float* __restrict__ b_ih1,
             const float* __restrict__ b_hh1) {
    extern __shared__ float sm[];
    float* wx   = sm;                   // 320
    float* bs   = wx + 320;             // 320
    float* hs   = bs + 320;             // 640    [k][b] plain
    float* gs   = hs + 640;             // 12800  [kg][bp][par][320]
    float* xall = gs + 12800;           // 4096   [b][t]

    const int tid = threadIdx.x;
    const int b0  = blockIdx.x * 8;

    for (int i = tid; i < G1; i += 512) { wx[i] = W_ih1[i]; bs[i] = b_ih1[i] + b_hh1[i]; }
    for (int i = tid; i < 640; i += 512) hs[i] = 0.0f;
    for (int i = tid; i < 8 * TT; i += 512) {
        int b = i >> 9, t = i & 511;
        xall[i] = x[(size_t)(b0 + b) * TT + t];
    }

    const bool act = tid < 400;
    const int  kg  = tid / 80;          // 5 k-groups of 16
    const int  jg  = tid - kg * 80;     // 80 j-groups of 4
    const int  j0  = jg * 4;
    const int  k0  = kg * 16;

    // W block -> registers (one-time LDG; g[j] = sum_k h[k]*W_hh1[j][k])
    float wreg[4][16];
    if (act) {
#pragma unroll
        for (int j = 0; j < 4; ++j)
#pragma unroll
            for (int kq = 0; kq < 4; ++kq)
                *(float4*)&wreg[j][kq * 4] =
                    *(const float4*)(W_hh1 + (size_t)(j0 + j) * H1C + k0 + kq * 4);
    }
    __syncthreads();

    // activation items: 640 (b,u) over 512 threads -> 1 or 2 (tid<128 -> 2)
    const int nit = (tid < 128) ? 2 : 1;
    int itb[2], itu[2];
    float cst[2] = {0.f, 0.f};
#pragma unroll
    for (int r = 0; r < 2; ++r) {
        int it = tid + 512 * r;
        itb[r] = it / 80;
        itu[r] = it - itb[r] * 80;
    }

    for (int t = 0; t < TT; ++t) {
        if (act) {
#pragma unroll
            for (int pass = 0; pass < 2; ++pass) {   // batches pass*4 .. pass*4+3
                float2 a[4][2];
#pragma unroll
                for (int j = 0; j < 4; ++j) { a[j][0] = make_float2(0.f, 0.f); a[j][1] = make_float2(0.f, 0.f); }
                const float* hp = hs + pass * 4 + k0 * 8;
#pragma unroll
                for (int k = 0; k < 16; ++k) {
                    float4 hv = *(const float4*)(hp + k * 8);  // broadcast, b-quad
                    float2 hq0 = make_float2(hv.x, hv.y);
                    float2 hq1 = make_float2(hv.z, hv.w);
#pragma unroll
                    for (int j = 0; j < 4; ++j) {
                        float2 wd = make_float2(wreg[j][k], wreg[j][k]);
                        a[j][0] = ffma2(a[j][0], wd, hq0);
                        a[j][1] = ffma2(a[j][1], wd, hq1);
                    }
                }
                // store: [kg][bp][par][320]
                float* gp = gs + kg * 2560 + pass * 2 * 640 + j0;
#pragma unroll
                for (int bq = 0; bq < 2; ++bq) {
                    *(float4*)(gp + bq * 640)       = make_float4(a[0][bq].x, a[1][bq].x, a[2][bq].x, a[3][bq].x);
                    *(float4*)(gp + bq * 640 + 320) = make_float4(a[0][bq].y, a[1][bq].y, a[2][bq].y, a[3][bq].y);
                }
            }
        }
        __syncthreads();

        // ---- activation: sum 5 partials + x*wx + bias (stride-1 gathers) ----
#pragma unroll
        for (int r = 0; r < 2; ++r) {
            if (r < nit) {
                const int b = itb[r], u = itu[r];
                const float xv = xall[b * TT + t];
                const float* gb = gs + ((b >> 1) * 2 + (b & 1)) * 320;
                float s0 = fmaf(xv, wx[u],       bs[u]);
                float s1 = fmaf(xv, wx[80 + u],  bs[80 + u]);
                float s2 = fmaf(xv, wx[160 + u], bs[160 + u]);
                float s3 = fmaf(xv, wx[240 + u], bs[240 + u]);
#pragma unroll
                for (int q = 0; q < 5; ++q) {
                    const float* gq = gb + q * 2560;
                    s0 += gq[u];
                    s1 += gq[80 + u];
                    s2 += gq[160 + u];
                    s3 += gq[240 + u];
                }
                float ig = sigma_(s0), fg = sigma_(s1), gg = tanha(s2), og = sigma_(s3);
                float c = fmaf(fg, cst[r], ig * gg);
                cst[r] = c;
                float h = og * tanha(c);
                hs[u * 8 + b] = h;
                g_h1[(size_t)t * (BB * H1C) + (size_t)(b0 + b) * H1C + u] = fmaxf(h, 0.0f);
            }
        }
        __syncthreads();
    }
}

// ---------------------------------------------------------------------------
// Kernel 2: xg2 = relu(h1) @ W_ih2^T + bias.  Persistent, 148 blocks, 512 thr.
// (fma-bound per wavefront audit; unchanged)
// ---------------------------------------------------------------------------
__global__ void __launch_bounds__(512, 1)
xg2_gemm_kernel(const float* __restrict__ W_ih2, const float* __restrict__ b_ih2,
                const float* __restrict__ b_hh2) {
    extern __shared__ float sm[];
    float* Wt   = sm;            // 80*400 = 32000 (transposed W_ih2)
    float* bias = Wt + 32000;    // 400
    float* As   = bias + 400;    // 64*80 = 5120

    const int tid = threadIdx.x;
    for (int i = tid; i < G2 * H1C; i += 512) {
        int jj = i / H1C, k = i - jj * H1C;
        Wt[k * G2 + jj] = W_ih2[i];
    }
    for (int i = tid; i < G2; i += 512) bias[i] = b_ih2[i] + b_hh2[i];

    const int  rg  = tid / 50;
    const int  cg  = tid - rg * 50;
    const bool act = tid < 400;
    const int  NT  = (TT * BB) / 64;   // 8192 tiles

    for (int tile = blockIdx.x; tile < NT; tile += gridDim.x) {
        size_t r0 = (size_t)tile * 64;
        __syncthreads();
        for (int i = tid; i < 64 * H1C; i += 512) As[i] = g_h1[r0 * H1C + i];
        __syncthreads();
        if (act) {
            float2 acc[8][4];
#pragma unroll
            for (int i = 0; i < 8; ++i)
#pragma unroll
                for (int p = 0; p < 4; ++p) acc[i][p] = make_float2(0.f, 0.f);
            const float* ap = As + rg * 8 * H1C;
            const float* wp = Wt + cg * 8;
#pragma unroll 2
            for (int k = 0; k < H1C; ++k) {
                float2 w0 = *(const float2*)(wp + k * G2);
                float2 w1 = *(const float2*)(wp + k * G2 + 2);
                float2 w2 = *(const float2*)(wp + k * G2 + 4);
                float2 w3 = *(const float2*)(wp + k * G2 + 6);
#pragma unroll
                for (int i = 0; i < 8; ++i) {
                    float aval = ap[i * H1C + k];
                    float2 ad = make_float2(aval, aval);
                    acc[i][0] = ffma2(acc[i][0], w0, ad);
                    acc[i][1] = ffma2(acc[i][1], w1, ad);
                    acc[i][2] = ffma2(acc[i][2], w2, ad);
                    acc[i][3] = ffma2(acc[i][3], w3, ad);
                }
            }
            const int c = cg * 8;
#pragma unroll
            for (int i = 0; i < 8; ++i) {
                size_t row = r0 + (size_t)rg * 8 + i;
                float* op = g_xg2 + row * G2 + c;
#pragma unroll
                for (int p = 0; p < 4; ++p) {
                    float2 v = acc[i][p];
                    v.x += bias[c + 2 * p];
                    v.y += bias[c + 2 * p + 1];
                    *(float2*)(op + 2 * p) = v;
                }
            }
        }
    }
}

// ---------------------------------------------------------------------------
// Dummy kernel: keeps lstm2 as the 4th launch for ncu's fixed -s window.
// ---------------------------------------------------------------------------
__global__ void dummy_kernel() {
    if (threadIdx.x == 0) g_dummy_sink[blockIdx.x] = 1;
}

// ---------------------------------------------------------------------------
// Kernel 3: layer-2 LSTM. 128 CTAs x 8 batches, 512 threads, persistent over T.
// W_hh2 REGISTER-RESIDENT: 500 active = 5 kg (20 k) x 100 jg (4 j), wreg[4][20].
// Batches in 2 half-passes. gs[kg][bp][par][400]. xg prefetch via LDG.
// Activations via MUFU.TANH.
// ---------------------------------------------------------------------------
__global__ void __launch_bounds__(512, 1)
lstm2_kernel(const float* __restrict__ W_hh2) {
    extern __shared__ float sm[];
    float* hs = sm;              // 800    [k][b] plain
    float* gs = hs + 800;        // 16000  [kg][bp][par][400]

    const int tid = threadIdx.x;
    const int b0  = blockIdx.x * 8;

    for (int i = tid; i < 800; i += 512) hs[i] = 0.0f;

    const bool act = tid < 500;
    const int  kg  = tid / 100;         // 5 k-groups of 20
    const int  jg  = tid - kg * 100;    // 100 j-groups of 4
    const int  j0  = jg * 4;
    const int  k0  = kg * 20;

    // W block -> registers (one-time LDG)
    float wreg[4][20];
    if (act) {
#pragma unroll
        for (int j = 0; j < 4; ++j)
#pragma unroll
            for (int kq = 0; kq < 5; ++kq)
                *(float4*)&wreg[j][kq * 4] =
                    *(const float4*)(W_hh2 + (size_t)(j0 + j) * H2C + k0 + kq * 4);
    }
    __syncthreads();

    // activation items: 800 over 512 threads -> 1 or 2 (tid<288 -> 2)
    const int nit = (tid < 288) ? 2 : 1;
    int itb[2], itu[2];
    float cst[2] = {0.f, 0.f};
#pragma unroll
    for (int r = 0; r < 2; ++r) {
        int it = tid + 512 * r;
        itb[r] = it / 100;
        itu[r] = it - itb[r] * 100;
    }

    for (int t = 0; t < TT; ++t) {
        // ---- prefetch xg (hidden by matvec) ----
        float xv[2][4];
#pragma unroll
        for (int r = 0; r < 2; ++r) {
            if (r < nit) {
                const float* xp = g_xg2 + (size_t)t * (BB * G2)
                                        + (size_t)(b0 + itb[r]) * G2 + itu[r];
                xv[r][0] = xp[0];
                xv[r][1] = xp[100];
                xv[r][2] = xp[200];
                xv[r][3] = xp[300];
            }
        }

        if (act) {
#pragma unroll
            for (int pass = 0; pass < 2; ++pass) {   // batches pass*4 .. pass*4+3
                float2 a[4][2];
#pragma unroll
                for (int j = 0; j < 4; ++j) { a[j][0] = make_float2(0.f, 0.f); a[j][1] = make_float2(0.f, 0.f); }
                const float* hp = hs + pass * 4 + k0 * 8;
#pragma unroll
                for (int k = 0; k < 20; ++k) {
                    float4 hv = *(const float4*)(hp + k * 8);  // broadcast, b-quad
                    float2 hq0 = make_float2(hv.x, hv.y);
                    float2 hq1 = make_float2(hv.z, hv.w);
#pragma unroll
                    for (int j = 0; j < 4; ++j) {
                        float2 wd = make_float2(wreg[j][k], wreg[j][k]);
                        a[j][0] = ffma2(a[j][0], wd, hq0);
                        a[j][1] = ffma2(a[j][1], wd, hq1);
                    }
                }
                // store: [kg][bp][par][400]
                float* gp = gs + kg * 3200 + pass * 2 * 800 + j0;
#pragma unroll
                for (int bq = 0; bq < 2; ++bq) {
                    *(float4*)(gp + bq * 800)       = make_float4(a[0][bq].x, a[1][bq].x, a[2][bq].x, a[3][bq].x);
                    *(float4*)(gp + bq * 800 + 400) = make_float4(a[0][bq].y, a[1][bq].y, a[2][bq].y, a[3][bq].y);
                }
            }
        }
        __syncthreads();

        // ---- activation: sum 5 partials + xg (stride-1 gathers) ----
#pragma unroll
        for (int r = 0; r < 2; ++r) {
            if (r < nit) {
                const int b = itb[r], u = itu[r];
                const float* gb = gs + ((b >> 1) * 2 + (b & 1)) * 400;
                float s0 = xv[r][0], s1 = xv[r][1], s2 = xv[r][2], s3 = xv[r][3];
#pragma unroll
                for (int q = 0; q < 5; ++q) {
                    const float* gq = gb + q * 3200;
                    s0 += gq[u];
                    s1 += gq[100 + u];
                    s2 += gq[200 + u];
                    s3 += gq[300 + u];
                }
                float ig = sigma_(s0), fg = sigma_(s1), gg = tanha(s2), og = sigma_(s3);
                float c = fmaf(fg, cst[r], ig * gg);
                cst[r] = c;
                float h = og * tanha(c);
                hs[u * 8 + b] = h;
                if (t == TT - 1) g_h2last[(b0 + b) * H2C + u] = fmaxf(h, 0.0f);
            }
        }
        __syncthreads();
    }
}

// ---------------------------------------------------------------------------
// Kernel 4: final MLP head.
// ---------------------------------------------------------------------------
__global__ void fc_kernel(const float* __restrict__ W_l1, const float* __restrict__ b_l1,
                          const float* __restrict__ W_l2, const float* __restrict__ b_l2,
                          float* __restrict__ out) {
    __shared__ float wl1[10 * 100];
    __shared__ float bl1[10], wl2[10], bl2s;
    const int tid = threadIdx.x;
    for (int i = tid; i < 1000; i += 256) wl1[i] = W_l1[i];
    if (tid < 10) { bl1[tid] = b_l1[tid]; wl2[tid] = W_l2[tid]; }
    if (tid == 0) bl2s = b_l2[0];
    __syncthreads();

    const int b = blockIdx.x * 256 + tid;
    float acc[10];
#pragma unroll
    for (int jj = 0; jj < 10; ++jj) acc[jj] = bl1[jj];
    const float* hp = g_h2last + b * H2C;
    for (int k = 0; k < H2C; ++k) {
        float hk = hp[k];
#pragma unroll
        for (int jj = 0; jj < 10; ++jj) acc[jj] = fmaf(wl1[jj * 100 + k], hk, acc[jj]);
    }
    float o = bl2s;
#pragma unroll
    for (int jj = 0; jj < 10; ++jj) o += wl2[jj] * fmaxf(acc[jj], 0.0f);
    out[b] = o;
}

// ---------------------------------------------------------------------------
extern "C" void kernel_launch(void* const* d_in, const int* in_sizes, int n_in,
                              void* d_out, int out_size) {
    const float* x     = (const float*)d_in[0];
    const float* W_ih1 = (const float*)d_in[1];
    const float* W_hh1 = (const float*)d_in[2];
    const float* b_ih1 = (const float*)d_in[3];
    const float* b_hh1 = (const float*)d_in[4];
    const float* W_ih2 = (const float*)d_in[5];
    const float* W_hh2 = (const float*)d_in[6];
    const float* b_ih2 = (const float*)d_in[7];
    const float* b_hh2 = (const float*)d_in[8];
    const float* W_l1  = (const float*)d_in[9];
    const float* b_l1  = (const float*)d_in[10];
    const float* W_l2  = (const float*)d_in[11];
    const float* b_l2  = (const float*)d_in[12];

    const size_t smA = (size_t)(320 + 320 + 640 + 12800 + 4096) * 4;  // 72704 B
    const size_t smG = (size_t)(32000 + 400 + 5120) * 4;              // 150080 B
    const size_t smB = (size_t)(800 + 16000) * 4;                     // 67200 B

    cudaFuncSetAttribute(lstm1_kernel,    cudaFuncAttributeMaxDynamicSharedMemorySize, (int)smA);
    cudaFuncSetAttribute(xg2_gemm_kernel, cudaFuncAttributeMaxDynamicSharedMemorySize, (int)smG);
    cudaFuncSetAttribute(lstm2_kernel,    cudaFuncAttributeMaxDynamicSharedMemorySize, (int)smB);

    lstm1_kernel<<<128, 512, smA>>>(x, W_ih1, W_hh1, b_ih1, b_hh1);
    xg2_gemm_kernel<<<148, 512, smG>>>(W_ih2, b_ih2, b_hh2);
    dummy_kernel<<<1, 32>>>();                                  // capture-window shim
    lstm2_kernel<<<128, 512, smB>>>(W_hh2);
    fc_kernel<<<4, 256>>>(W_l1, b_l1, W_l2, b_l2, (float*)d_out);
}

// round 16
// speedup vs baseline: 1.3263x; 1.0327x over previous
#include <cuda_runtime.h>

#define BB 1024
#define TT 512
#define H1C 80
#define G1 320
#define H2C 100
#define G2 400

// Scratch (static device arrays: allocation-free per harness rules)
__device__ float g_h1[(size_t)TT * BB * H1C];      // relu(h1): 168 MB, layout [t][b][u]
__device__ float g_xg2[(size_t)TT * BB * G2];      // layer-2 gate pre-acts: 839 MB, [t][b][g]
__device__ float g_h2last[BB * H2C];               // relu(h2) at t=T-1
__device__ int   g_dummy_sink[32];

__device__ __forceinline__ float2 ffma2(float2 d, float2 a, float2 b) {
    unsigned long long dd = *reinterpret_cast<unsigned long long*>(&d);
    unsigned long long aa = *reinterpret_cast<unsigned long long*>(&a);
    unsigned long long bb = *reinterpret_cast<unsigned long long*>(&b);
    asm("fma.rn.f32x2 %0, %1, %2, %0;" : "+l"(dd) : "l"(aa), "l"(bb));
    return *reinterpret_cast<float2*>(&dd);
}

__device__ __forceinline__ float tanha(float x) {
    float y; asm("tanh.approx.f32 %0, %1;" : "=f"(y) : "f"(x)); return y;
}
__device__ __forceinline__ float sigma_(float x) { return fmaf(0.5f, tanha(0.5f * x), 0.5f); }

// ---------------------------------------------------------------------------
// Kernel 1: layer-1 LSTM. 128 CTAs x 8 batches, 512 threads, persistent over T.
// W_hh1 REGISTER-RESIDENT: 400 mv threads = 5 kg (16 k) x 80 jg (4 j), wreg[4][16].
// SINGLE-PASS matvec acc[4][4] (all 8 batches at once; (w,w) dups shared).
// Activation: u-PAIR items -> 320 threads x exactly 1 item; float2 gathers/stores.
// gs[kg][bp][par][320]: coalesced STS.128 stores, stride-1 float2 gathers.
// ---------------------------------------------------------------------------
__global__ void __launch_bounds__(512, 1)
lstm1_kernel(const float* __restrict__ x, const float* __restrict__ W_ih1,
             const float* __restrict__ W_hh1, const float* __restrict__ b_ih1,
             const float* __restrict__ b_hh1) {
    extern __shared__ float sm[];
    float* wx   = sm;                   // 320
    float* bs   = wx + 320;             // 320
    float* hs   = bs + 320;             // 640    [k][b] plain
    float* gs   = hs + 640;             // 12800  [kg][bp][par][320]
    float* xall = gs + 12800;           // 4096   [b][t]

    const int tid = threadIdx.x;
    const int b0  = blockIdx.x * 8;

    for (int i = tid; i < G1; i += 512) { wx[i] = W_ih1[i]; bs[i] = b_ih1[i] + b_hh1[i]; }
    for (int i = tid; i < 640; i += 512) hs[i] = 0.0f;
    for (int i = tid; i < 8 * TT; i += 512) {
        int b = i >> 9, t = i & 511;
        xall[i] = x[(size_t)(b0 + b) * TT + t];
    }

    const bool mvact = tid < 400;
    const int  kg  = tid / 80;          // 5 k-groups of 16
    const int  jg  = tid - kg * 80;     // 80 j-groups of 4
    const int  j0  = jg * 4;
    const int  k0  = kg * 16;

    // W block -> registers (one-time LDG; g[j] = sum_k h[k]*W_hh1[j][k])
    float wreg[4][16];
    if (mvact) {
#pragma unroll
        for (int j = 0; j < 4; ++j)
#pragma unroll
            for (int kq = 0; kq < 4; ++kq)
                *(float4*)&wreg[j][kq * 4] =
                    *(const float4*)(W_hh1 + (size_t)(j0 + j) * H1C + k0 + kq * 4);
    }
    __syncthreads();

    // activation items: (b, u-pair): 8 b x 40 up = 320 items, exactly 1 per thread
    const bool has_item = tid < 320;
    const int  ib = tid / 40;           // batch 0..7
    const int  up = tid - ib * 40;      // u-pair 0..39 (u0 = 2*up)
    float2 cst = make_float2(0.f, 0.f);

    for (int t = 0; t < TT; ++t) {
        if (mvact) {
            float2 a[4][4];             // [j][bpair], all 8 batches
#pragma unroll
            for (int j = 0; j < 4; ++j)
#pragma unroll
                for (int bp = 0; bp < 4; ++bp) a[j][bp] = make_float2(0.f, 0.f);
            const float* hp = hs + k0 * 8;
#pragma unroll
            for (int k = 0; k < 16; ++k) {
                float4 hA = *(const float4*)(hp + k * 8);      // b0..3 (broadcast)
                float4 hB = *(const float4*)(hp + k * 8 + 4);  // b4..7
                float2 hq0 = make_float2(hA.x, hA.y);
                float2 hq1 = make_float2(hA.z, hA.w);
                float2 hq2 = make_float2(hB.x, hB.y);
                float2 hq3 = make_float2(hB.z, hB.w);
#pragma unroll
                for (int j = 0; j < 4; ++j) {
                    float2 wd = make_float2(wreg[j][k], wreg[j][k]);
                    a[j][0] = ffma2(a[j][0], wd, hq0);
                    a[j][1] = ffma2(a[j][1], wd, hq1);
                    a[j][2] = ffma2(a[j][2], wd, hq2);
                    a[j][3] = ffma2(a[j][3], wd, hq3);
                }
            }
            // store: [kg][bp][par][320]
            float* gp = gs + kg * 2560 + j0;
#pragma unroll
            for (int bp = 0; bp < 4; ++bp) {
                *(float4*)(gp + bp * 640)       = make_float4(a[0][bp].x, a[1][bp].x, a[2][bp].x, a[3][bp].x);
                *(float4*)(gp + bp * 640 + 320) = make_float4(a[0][bp].y, a[1][bp].y, a[2][bp].y, a[3][bp].y);
            }
        }
        __syncthreads();

        // ---- activation: u-pair items, float2 gathers (stride-1) ----
        if (has_item) {
            const float xvs = xall[ib * TT + t];
            const float2* wx2 = (const float2*)wx;
            const float2* bs2 = (const float2*)bs;
            float2 s0 = make_float2(fmaf(xvs, wx2[up].x,       bs2[up].x),
                                    fmaf(xvs, wx2[up].y,       bs2[up].y));
            float2 s1 = make_float2(fmaf(xvs, wx2[40 + up].x,  bs2[40 + up].x),
                                    fmaf(xvs, wx2[40 + up].y,  bs2[40 + up].y));
            float2 s2 = make_float2(fmaf(xvs, wx2[80 + up].x,  bs2[80 + up].x),
                                    fmaf(xvs, wx2[80 + up].y,  bs2[80 + up].y));
            float2 s3 = make_float2(fmaf(xvs, wx2[120 + up].x, bs2[120 + up].x),
                                    fmaf(xvs, wx2[120 + up].y, bs2[120 + up].y));
            const float* gb = gs + ((ib >> 1) * 2 + (ib & 1)) * 320;
#pragma unroll
            for (int q = 0; q < 5; ++q) {
                const float2* gq = (const float2*)(gb + q * 2560);
                float2 v0 = gq[up], v1 = gq[40 + up], v2 = gq[80 + up], v3 = gq[120 + up];
                s0.x += v0.x; s0.y += v0.y;
                s1.x += v1.x; s1.y += v1.y;
                s2.x += v2.x; s2.y += v2.y;
                s3.x += v3.x; s3.y += v3.y;
            }
            float igx = sigma_(s0.x), igy = sigma_(s0.y);
            float fgx = sigma_(s1.x), fgy = sigma_(s1.y);
            float ggx = tanha(s2.x),  ggy = tanha(s2.y);
            float ogx = sigma_(s3.x), ogy = sigma_(s3.y);
            float cx = fmaf(fgx, cst.x, igx * ggx);
            float cy = fmaf(fgy, cst.y, igy * ggy);
            cst = make_float2(cx, cy);
            float hx = ogx * tanha(cx);
            float hy = ogy * tanha(cy);
            const int u0 = up * 2;
            hs[u0 * 8 + ib]       = hx;
            hs[(u0 + 1) * 8 + ib] = hy;
            *(float2*)&g_h1[(size_t)t * (BB * H1C) + (size_t)(b0 + ib) * H1C + u0] =
                make_float2(fmaxf(hx, 0.0f), fmaxf(hy, 0.0f));
        }
        __syncthreads();
    }
}

// ---------------------------------------------------------------------------
// Kernel 2: xg2 = relu(h1) @ W_ih2^T + bias.  Persistent, 148 blocks, 512 thr.
// (fma-bound per wavefront audit; unchanged)
// ---------------------------------------------------------------------------
__global__ void __launch_bounds__(512, 1)
xg2_gemm_kernel(const float* __restrict__ W_ih2, const float* __restrict__ b_ih2,
                const float* __restrict__ b_hh2) {
    extern __shared__ float sm[];
    float* Wt   = sm;            // 80*400 = 32000 (transposed W_ih2)
    float* bias = Wt + 32000;    // 400
    float* As   = bias + 400;    // 64*80 = 5120

    const int tid = threadIdx.x;
    for (int i = tid; i < G2 * H1C; i += 512) {
        int jj = i / H1C, k = i - jj * H1C;
        Wt[k * G2 + jj] = W_ih2[i];
    }
    for (int i = tid; i < G2; i += 512) bias[i] = b_ih2[i] + b_hh2[i];

    const int  rg  = tid / 50;
    const int  cg  = tid - rg * 50;
    const bool act = tid < 400;
    const int  NT  = (TT * BB) / 64;   // 8192 tiles

    for (int tile = blockIdx.x; tile < NT; tile += gridDim.x) {
        size_t r0 = (size_t)tile * 64;
        __syncthreads();
        for (int i = tid; i < 64 * H1C; i += 512) As[i] = g_h1[r0 * H1C + i];
        __syncthreads();
        if (act) {
            float2 acc[8][4];
#pragma unroll
            for (int i = 0; i < 8; ++i)
#pragma unroll
                for (int p = 0; p < 4; ++p) acc[i][p] = make_float2(0.f, 0.f);
            const float* ap = As + rg * 8 * H1C;
            const float* wp = Wt + cg * 8;
#pragma unroll 2
            for (int k = 0; k < H1C; ++k) {
                float2 w0 = *(const float2*)(wp + k * G2);
                float2 w1 = *(const float2*)(wp + k * G2 + 2);
                float2 w2 = *(const float2*)(wp + k * G2 + 4);
                float2 w3 = *(const float2*)(wp + k * G2 + 6);
#pragma unroll
                for (int i = 0; i < 8; ++i) {
                    float aval = ap[i * H1C + k];
                    float2 ad = make_float2(aval, aval);
                    acc[i][0] = ffma2(acc[i][0], w0, ad);
                    acc[i][1] = ffma2(acc[i][1], w1, ad);
                    acc[i][2] = ffma2(acc[i][2], w2, ad);
                    acc[i][3] = ffma2(acc[i][3], w3, ad);
                }
            }
            const int c = cg * 8;
#pragma unroll
            for (int i = 0; i < 8; ++i) {
                size_t row = r0 + (size_t)rg * 8 + i;
                float* op = g_xg2 + row * G2 + c;
#pragma unroll
                for (int p = 0; p < 4; ++p) {
                    float2 v = acc[i][p];
                    v.x += bias[c + 2 * p];
                    v.y += bias[c + 2 * p + 1];
                    *(float2*)(op + 2 * p) = v;
                }
            }
        }
    }
}

// ---------------------------------------------------------------------------
// Dummy kernel: keeps lstm2 as the 4th launch for ncu's fixed -s window.
// ---------------------------------------------------------------------------
__global__ void dummy_kernel() {
    if (threadIdx.x == 0) g_dummy_sink[blockIdx.x] = 1;
}

// ---------------------------------------------------------------------------
// Kernel 3: layer-2 LSTM. 128 CTAs x 8 batches, 512 threads, persistent over T.
// W_hh2 REGISTER-RESIDENT: 500 mv threads = 5 kg (20 k) x 100 jg (4 j), wreg[4][20].
// Matvec 2-pass (reg safety at 80 W-regs). Activation: u-PAIR items -> 400
// threads x 1 item; float2 xg prefetch + float2 gathers.
// ---------------------------------------------------------------------------
__global__ void __launch_bounds__(512, 1)
lstm2_kernel(const float* __restrict__ W_hh2) {
    extern __shared__ float sm[];
    float* hs = sm;              // 800    [k][b] plain
    float* gs = hs + 800;        // 16000  [kg][bp][par][400]

    const int tid = threadIdx.x;
    const int b0  = blockIdx.x * 8;

    for (int i = tid; i < 800; i += 512) hs[i] = 0.0f;

    const bool mvact = tid < 500;
    const int  kg  = tid / 100;         // 5 k-groups of 20
    const int  jg  = tid - kg * 100;    // 100 j-groups of 4
    const int  j0  = jg * 4;
    const int  k0  = kg * 20;

    // W block -> registers (one-time LDG)
    float wreg[4][20];
    if (mvact) {
#pragma unroll
        for (int j = 0; j < 4; ++j)
#pragma unroll
            for (int kq = 0; kq < 5; ++kq)
                *(float4*)&wreg[j][kq * 4] =
                    *(const float4*)(W_hh2 + (size_t)(j0 + j) * H2C + k0 + kq * 4);
    }
    __syncthreads();

    // activation items: (b, u-pair): 8 b x 50 up = 400 items, exactly 1 per thread
    const bool has_item = tid < 400;
    const int  ib = tid / 50;           // batch 0..7
    const int  up = tid - ib * 50;      // u-pair 0..49 (u0 = 2*up)
    float2 cst = make_float2(0.f, 0.f);

    for (int t = 0; t < TT; ++t) {
        // ---- prefetch xg as float2 (hidden by matvec) ----
        float2 xv0, xv1, xv2, xv3;
        if (has_item) {
            const float* xp = g_xg2 + (size_t)t * (BB * G2)
                                    + (size_t)(b0 + ib) * G2 + up * 2;
            xv0 = *(const float2*)(xp);
            xv1 = *(const float2*)(xp + 100);
            xv2 = *(const float2*)(xp + 200);
            xv3 = *(const float2*)(xp + 300);
        }

        if (mvact) {
#pragma unroll
            for (int pass = 0; pass < 2; ++pass) {   // batches pass*4 .. pass*4+3
                float2 a[4][2];
#pragma unroll
                for (int j = 0; j < 4; ++j) { a[j][0] = make_float2(0.f, 0.f); a[j][1] = make_float2(0.f, 0.f); }
                const float* hp = hs + pass * 4 + k0 * 8;
#pragma unroll
                for (int k = 0; k < 20; ++k) {
                    float4 hv = *(const float4*)(hp + k * 8);  // broadcast, b-quad
                    float2 hq0 = make_float2(hv.x, hv.y);
                    float2 hq1 = make_float2(hv.z, hv.w);
#pragma unroll
                    for (int j = 0; j < 4; ++j) {
                        float2 wd = make_float2(wreg[j][k], wreg[j][k]);
                        a[j][0] = ffma2(a[j][0], wd, hq0);
                        a[j][1] = ffma2(a[j][1], wd, hq1);
                    }
                }
                // store: [kg][bp][par][400]
                float* gp = gs + kg * 3200 + pass * 2 * 800 + j0;
#pragma unroll
                for (int bq = 0; bq < 2; ++bq) {
                    *(float4*)(gp + bq * 800)       = make_float4(a[0][bq].x, a[1][bq].x, a[2][bq].x, a[3][bq].x);
                    *(float4*)(gp + bq * 800 + 400) = make_float4(a[0][bq].y, a[1][bq].y, a[2][bq].y, a[3][bq].y);
                }
            }
        }
        __syncthreads();

        // ---- activation: u-pair items, float2 gathers (stride-1) ----
        if (has_item) {
            float2 s0 = xv0, s1 = xv1, s2 = xv2, s3 = xv3;
            const float* gb = gs + ((ib >> 1) * 2 + (ib & 1)) * 400;
#pragma unroll
            for (int q = 0; q < 5; ++q) {
                const float2* gq = (const float2*)(gb + q * 3200);
                float2 v0 = gq[up], v1 = gq[50 + up], v2 = gq[100 + up], v3 = gq[150 + up];
                s0.x += v0.x; s0.y += v0.y;
                s1.x += v1.x; s1.y += v1.y;
                s2.x += v2.x; s2.y += v2.y;
                s3.x += v3.x; s3.y += v3.y;
            }
            float igx = sigma_(s0.x), igy = sigma_(s0.y);
            float fgx = sigma_(s1.x), fgy = sigma_(s1.y);
            float ggx = tanha(s2.x),  ggy = tanha(s2.y);
            float ogx = sigma_(s3.x), ogy = sigma_(s3.y);
            float cx = fmaf(fgx, cst.x, igx * ggx);
            float cy = fmaf(fgy, cst.y, igy * ggy);
            cst = make_float2(cx, cy);
            float hx = ogx * tanha(cx);
            float hy = ogy * tanha(cy);
            const int u0 = up * 2;
            hs[u0 * 8 + ib]       = hx;
            hs[(u0 + 1) * 8 + ib] = hy;
            if (t == TT - 1)
                *(float2*)&g_h2last[(b0 + ib) * H2C + u0] =
                    make_float2(fmaxf(hx, 0.0f), fmaxf(hy, 0.0f));
        }
        __syncthreads();
    }
}

// ---------------------------------------------------------------------------
// Kernel 4: final MLP head.
// ---------------------------------------------------------------------------
__global__ void fc_kernel(const float* __restrict__ W_l1, const float* __restrict__ b_l1,
                          const float* __restrict__ W_l2, const float* __restrict__ b_l2,
                          float* __restrict__ out) {
    __shared__ float wl1[10 * 100];
    __shared__ float bl1[10], wl2[10], bl2s;
    const int tid = threadIdx.x;
    for (int i = tid; i < 1000; i += 256) wl1[i] = W_l1[i];
    if (tid < 10) { bl1[tid] = b_l1[tid]; wl2[tid] = W_l2[tid]; }
    if (tid == 0) bl2s = b_l2[0];
    __syncthreads();

    const int b = blockIdx.x * 256 + tid;
    float acc[10];
#pragma unroll
    for (int jj = 0; jj < 10; ++jj) acc[jj] = bl1[jj];
    const float* hp = g_h2last + b * H2C;
    for (int k = 0; k < H2C; ++k) {
        float hk = hp[k];
#pragma unroll
        for (int jj = 0; jj < 10; ++jj) acc[jj] = fmaf(wl1[jj * 100 + k], hk, acc[jj]);
    }
    float o = bl2s;
#pragma unroll
    for (int jj = 0; jj < 10; ++jj) o += wl2[jj] * fmaxf(acc[jj], 0.0f);
    out[b] = o;
}

// ---------------------------------------------------------------------------
extern "C" void kernel_launch(void* const* d_in, const int* in_sizes, int n_in,
                              void* d_out, int out_size) {
    const float* x     = (const float*)d_in[0];
    const float* W_ih1 = (const float*)d_in[1];
    const float* W_hh1 = (const float*)d_in[2];
    const float* b_ih1 = (const float*)d_in[3];
    const float* b_hh1 = (const float*)d_in[4];
    const float* W_ih2 = (const float*)d_in[5];
    const float* W_hh2 = (const float*)d_in[6];
    const float* b_ih2 = (const float*)d_in[7];
    const float* b_hh2 = (const float*)d_in[8];
    const float* W_l1  = (const float*)d_in[9];
    const float* b_l1  = (const float*)d_in[10];
    const float* W_l2  = (const float*)d_in[11];
    const float* b_l2  = (const float*)d_in[12];

    const size_t smA = (size_t)(320 + 320 + 640 + 12800 + 4096) * 4;  // 72704 B
    const size_t smG = (size_t)(32000 + 400 + 5120) * 4;              // 150080 B
    const size_t smB = (size_t)(800 + 16000) * 4;                     // 67200 B

    cudaFuncSetAttribute(lstm1_kernel,    cudaFuncAttributeMaxDynamicSharedMemorySize, (int)smA);
    cudaFuncSetAttribute(xg2_gemm_kernel, cudaFuncAttributeMaxDynamicSharedMemorySize, (int)smG);
    cudaFuncSetAttribute(lstm2_kernel,    cudaFuncAttributeMaxDynamicSharedMemorySize, (int)smB);

    lstm1_kernel<<<128, 512, smA>>>(x, W_ih1, W_hh1, b_ih1, b_hh1);
    xg2_gemm_kernel<<<148, 512, smG>>>(W_ih2, b_ih2, b_hh2);
    dummy_kernel<<<1, 32>>>();                                  // capture-window shim
    lstm2_kernel<<<128, 512, smB>>>(W_hh2);
    fc_kernel<<<4, 256>>>(W_l1, b_l1, W_l2, b_l2, (float*)d_out);
}